// round 15
// baseline (speedup 1.0000x reference)
#include <cuda_runtime.h>
#include <cuda_fp16.h>
#include <cstdint>

// ---------------- problem constants ----------------
#define B_     8
#define CIN    64
#define COUT   128
#define HP     66
#define WP     66
#define FDIM   448               // 64 ch * 7 features
#define KDIM   4032              // 9 taps * 448
#define NPIX   32768
#define PATCH  576
#define NCHUNK 126               // K chunks of 32
#define HCHUNK 63                // chunks per K-group (63 = 7*9)

#define FEAT_BLOCKS ((B_*HP*WP*16)/256)            // 2178 (4 ch/thread)
#define PACK_BLOCKS ((COUT*KDIM + 255)/256)        // 2016

// ---------------- scratch (device globals) ----------------
__device__ __half   g_Fh[(size_t)B_*HP*WP*FDIM];     // 31.2 MB fp16 features
__device__ uint4    g_Wp[(size_t)COUT*KDIM/8];       // 1 MB weights in mma-frag order
__device__ uint32_t g_offA[NCHUNK];                  // per-chunk A element offsets

// ---------------- PTX helpers ----------------
__device__ __forceinline__ uint32_t smem_u32(const void* p) {
    uint32_t a;
    asm("{ .reg .u64 t; cvta.to.shared.u64 t, %1; cvt.u32.u64 %0, t; }"
        : "=r"(a) : "l"(p));
    return a;
}
__device__ __forceinline__ void cpasync16(uint32_t sa, const void* g) {
    asm volatile("cp.async.cg.shared.global [%0], [%1], 16;"
                 :: "r"(sa), "l"(g) : "memory");
}
__device__ __forceinline__ void cp_commit() {
    asm volatile("cp.async.commit_group;" ::: "memory");
}
__device__ __forceinline__ void cp_wait1() {
    asm volatile("cp.async.wait_group 1;" ::: "memory");
}
__device__ __forceinline__ void bar_grp(int id) {
    asm volatile("bar.sync %0, 128;" :: "r"(id) : "memory");
}
__device__ __forceinline__ void ldsm4(uint32_t* r, uint32_t addr) {
    asm volatile("ldmatrix.sync.aligned.m8n8.x4.shared.b16 {%0,%1,%2,%3}, [%4];"
                 : "=r"(r[0]), "=r"(r[1]), "=r"(r[2]), "=r"(r[3]) : "r"(addr));
}
__device__ __forceinline__ void mma16816(float* d, const uint32_t* a, uint32_t b0, uint32_t b1) {
    asm volatile(
        "mma.sync.aligned.m16n8k16.row.col.f32.f16.f16.f32 "
        "{%0,%1,%2,%3}, {%4,%5,%6,%7}, {%8,%9}, {%0,%1,%2,%3};"
        : "+f"(d[0]), "+f"(d[1]), "+f"(d[2]), "+f"(d[3])
        : "r"(a[0]), "r"(a[1]), "r"(a[2]), "r"(a[3]), "r"(b0), "r"(b1));
}
__device__ __forceinline__ uint32_t h2_bits(float a, float b) {
    half2 h = __floats2half2_rn(a, b);
    return *reinterpret_cast<uint32_t*>(&h);
}

// ---------------- Cox–de Boor features ----------------
__device__ __forceinline__ void eval_features(float v, float* f)
{
    const float hh = 2.0f / 3.0f;
    float g[10];
    #pragma unroll
    for (int j = 0; j < 10; j++) g[j] = (float)(j - 3) * hh - 1.0f;

    float bas[9];
    #pragma unroll
    for (int i = 0; i < 9; i++)
        bas[i] = (v >= g[i] && v < g[i+1]) ? 1.0f : 0.0f;
    const float rp1 = 1.5f, rp2 = 0.75f, rp3 = 0.5f;
    #pragma unroll
    for (int i = 0; i < 8; i++)
        bas[i] = (v - g[i]) * rp1 * bas[i] + (g[i+2] - v) * rp1 * bas[i+1];
    #pragma unroll
    for (int i = 0; i < 7; i++)
        bas[i] = (v - g[i]) * rp2 * bas[i] + (g[i+3] - v) * rp2 * bas[i+1];
    #pragma unroll
    for (int i = 0; i < 6; i++)
        bas[i] = (v - g[i]) * rp3 * bas[i] + (g[i+4] - v) * rp3 * bas[i+1];

    f[0] = v / (1.0f + __expf(-v));   // silu
    #pragma unroll
    for (int m = 0; m < 6; m++) f[m+1] = bas[m];
}

// ---------------- kernel 1: fused feature + weight pack + offset table ----------
// Weight frag layout (R12): frag16 idx = ((chunk*4 + wn)*4 + nt)*32 + lane
//   wn = o>>5 (32-col group), nt = (o>>3)&3, lane = (o&7)*4 + ((k&7)>>1)
//   pos = ((k>>4)&1)*4 + ((k>>3)&1)*2 + (k&1), chunk = k>>5
__global__ void prep_kernel(const float* __restrict__ x,
                            const float* __restrict__ base_w,
                            const float* __restrict__ spline_w)
{
    if (blockIdx.x < FEAT_BLOCKS) {
        int idx = blockIdx.x * blockDim.x + threadIdx.x;  // (pixel, channel-quad)
        int cq = idx & 15;
        int r  = idx >> 4;
        int wp = r % WP; r /= WP;
        int hp = r % HP;
        int b  = r / HP;

        int h = hp - 1, w = wp - 1;
        float4 xv = make_float4(0.f, 0.f, 0.f, 0.f);
        if (h >= 0 && h < 64 && w >= 0 && w < 64)
            xv = *(const float4*)&x[((((size_t)b*64 + h)*64 + w) << 6) + cq*4];

        float f0[7], f1[7], f2[7], f3[7];
        eval_features(xv.x, f0);
        eval_features(xv.y, f1);
        eval_features(xv.z, f2);
        eval_features(xv.w, f3);

        size_t base = (((size_t)b*HP + hp)*WP + wp)*FDIM + cq*4;
        #pragma unroll
        for (int m = 0; m < 7; m++) {
            uint2 pk;
            pk.x = h2_bits(f0[m], f1[m]);
            pk.y = h2_bits(f2[m], f3[m]);
            *(uint2*)&g_Fh[base + (size_t)m*64] = pk;
        }
    } else if (blockIdx.x < FEAT_BLOCKS + PACK_BLOCKS) {
        int idx = (blockIdx.x - FEAT_BLOCKS) * blockDim.x + threadIdx.x; // o*4032+k
        if (idx >= COUT * KDIM) return;
        int o = idx / KDIM;
        int k = idx - o * KDIM;
        int t = k / FDIM;
        int rr = k - t * FDIM;
        int f  = rr >> 6;
        int cc = rr & 63;
        int i  = cc * 9 + t;
        float wv = (f == 0) ? base_w[(size_t)o * PATCH + i]
                            : spline_w[((size_t)o * PATCH + i) * 6 + (f - 1)];

        int chunk = k >> 5;
        int wn    = o >> 5;
        int nt    = (o >> 3) & 3;
        int lane  = ((o & 7) << 2) | ((k & 7) >> 1);
        int pos   = ((k >> 4) & 1) * 4 + ((k >> 3) & 1) * 2 + (k & 1);
        size_t idx16 = (((size_t)chunk*4 + wn)*4 + nt)*32 + lane;
        ((__half*)g_Wp)[idx16 * 8 + pos] = __float2half(wv);
    } else {
        int c = threadIdx.x;
        if (c < NCHUNK) {
            int t  = c / 14;
            int rr = c - t * 14;
            int f  = rr >> 1;
            int c0 = (rr & 1) << 5;
            int ky = t / 3;
            int kx = t - ky * 3;
            g_offA[c] = (uint32_t)((ky * WP + kx) * FDIM + f * 64 + c0);
        }
    }
}

// ---------------- kernel 2: GEMM, M32xN128, split-K, 3 CTAs/SM -----------------
// 1024 CTAs x 256 threads, 3 CTAs/SM (85-reg cap -> 24 warps/SM = 6/SMSP).
// CTA tile: M=32, N=128, K=4032. 8 warps = 2 K-groups x 4 N-warps; warp tile
// M32 x N32 (acc 32 regs). B fragments LDG.128'd transiently per chunk
// (L1-resident stream; latency hidden by occupancy). 9-slot smem A pipeline;
// cp.wait + named group barrier once per 3-chunk window.
#define NSLOT  9
#define PITCH  80
#define STAGEB (32*PITCH)                 // 2560 B
#define REGION (NSLOT*STAGEB)             // 23040 B per K-group
#define RED_PITCH 132
#define DYN_SMEM (2*REGION)               // 46080 B (> 32*132*4 = 16896 epilogue)

__global__ void __launch_bounds__(256, 3)
gemm_kernel(const float* __restrict__ bias, float* __restrict__ out)
{
    extern __shared__ char dyn[];
    const uint32_t smbase = smem_u32(dyn);

    const int tid  = threadIdx.x;
    const int wid  = tid >> 5;
    const int lane = tid & 31;
    const int ks   = wid >> 2;              // K-group 0/1
    const int wn   = wid & 3;               // 32-col N group

    const int pixBase = blockIdx.x * 32;
    const int bimg    = pixBase >> 12;
    const int h0      = (pixBase >> 6) & 63;
    const int w0      = pixBase & 63;

    // ---- A cp.async geometry: each K-group's 128 threads load their own chunk
    const int rrow = (tid & 127) >> 2;      // 0..31
    const int seg  = tid & 3;
    const uint32_t baseA = (uint32_t)((((bimg*HP + h0)*WP) + (w0 + rrow))*FDIM) + seg*8;
    const uint32_t dstA  = smbase + ks * REGION + rrow * PITCH + seg * 16;

    // ---- A ldmatrix geometry (4 warps of a K-group share the same fragments)
    const uint32_t pA = smbase + ks * REGION + (lane & 15) * PITCH + (lane >> 4) * 16;

    // ---- B LDG geometry: frag16 idx = ((chunk*4 + wn)*4 + nt)*32 + lane
    const uint4* wpBase = g_Wp + (size_t)wn * 128 + lane;   // chunk stride 512, nt +32
    const int cBase = ks * HCHUNK;

    float acc[2][4][4];
    #pragma unroll
    for (int mt = 0; mt < 2; mt++)
        #pragma unroll
        for (int nt = 0; nt < 4; nt++)
            #pragma unroll
            for (int q = 0; q < 4; q++) acc[mt][nt][q] = 0.0f;

    auto produce = [&](int i, int s) {
        const uint32_t off = g_offA[cBase + i];
        cpasync16(dstA + s * STAGEB, g_Fh + baseA + off);
    };

    // prologue: windows -2,-1 (chunks 0..2 and 3..5)
    #pragma unroll
    for (int p = 0; p < 3; p++) produce(p, p);
    cp_commit();
    #pragma unroll
    for (int p = 3; p < 6; p++) produce(p, p);
    cp_commit();

    const int barid = ks + 1;

    // one chunk: B frags LDG'd transiently (L1 hit), compute from slot s
    auto body = [&](int i, int s) {
        const uint4* w = wpBase + (size_t)(cBase + i) * 512;
        uint4 b[4];
        #pragma unroll
        for (int nt = 0; nt < 4; nt++) b[nt] = w[nt * 32];

        const uint32_t so = s * STAGEB;
        uint32_t a00[4], a10[4], a01[4], a11[4];
        ldsm4(a00, pA + so);                        // mt=0, kk=0
        ldsm4(a10, pA + so + 16*PITCH);             // mt=1, kk=0
        ldsm4(a01, pA + so + 32);                   // mt=0, kk=1
        ldsm4(a11, pA + so + 16*PITCH + 32);        // mt=1, kk=1
        #pragma unroll
        for (int nt = 0; nt < 4; nt++) {
            mma16816(acc[0][nt], a00, b[nt].x, b[nt].y);
            mma16816(acc[1][nt], a10, b[nt].x, b[nt].y);
        }
        #pragma unroll
        for (int nt = 0; nt < 4; nt++) {
            mma16816(acc[0][nt], a01, b[nt].z, b[nt].w);
            mma16816(acc[1][nt], a11, b[nt].z, b[nt].w);
        }
    };

    // one 3-chunk window: reads slots sB..sB+2, produces i+6..i+8 into wB..wB+2
    auto window = [&](int i, int sB, int wB) {
        cp_wait1();            // window's own read group fully landed
        bar_grp(barid);        // group-wide visibility + prev-window reads done
        if (i + 6 < HCHUNK) {
            produce(i + 6, wB);
            produce(i + 7, wB + 1);
            produce(i + 8, wB + 2);
        }
        cp_commit();           // empty groups keep wait accounting exact
        body(i,     sB);
        body(i + 1, sB + 1);
        body(i + 2, sB + 2);
    };

    #pragma unroll 1
    for (int w = 0; w < HCHUNK; w += 9) {   // 63 = 7 * 9
        window(w,     0, 6);
        window(w + 3, 3, 0);
        window(w + 6, 6, 3);
    }

    // ---- epilogue: reduce the two K-group partials via smem, + bias, store ----
    __syncthreads();
    float* red = (float*)dyn;   // [32][RED_PITCH]
    const int colb0 = wn*32 + (lane & 3)*2;
    const int row0  = lane >> 2;

    if (ks == 1) {
        #pragma unroll
        for (int mt = 0; mt < 2; mt++)
            #pragma unroll
            for (int nt = 0; nt < 4; nt++) {
                const int col = colb0 + nt*8;
                *(float2*)&red[(mt*16 + row0    ) * RED_PITCH + col] =
                    make_float2(acc[mt][nt][0], acc[mt][nt][1]);
                *(float2*)&red[(mt*16 + row0 + 8) * RED_PITCH + col] =
                    make_float2(acc[mt][nt][2], acc[mt][nt][3]);
            }
    }
    __syncthreads();
    if (ks == 0) {
        #pragma unroll
        for (int mt = 0; mt < 2; mt++)
            #pragma unroll
            for (int nt = 0; nt < 4; nt++) {
                const int col = colb0 + nt*8;
                const float2 b2 = *(const float2*)(bias + col);
                float2 p0 = *(float2*)&red[(mt*16 + row0    ) * RED_PITCH + col];
                float2 p1 = *(float2*)&red[(mt*16 + row0 + 8) * RED_PITCH + col];
                float2 v0, v1;
                v0.x = acc[mt][nt][0] + p0.x + b2.x;
                v0.y = acc[mt][nt][1] + p0.y + b2.y;
                v1.x = acc[mt][nt][2] + p1.x + b2.x;
                v1.y = acc[mt][nt][3] + p1.y + b2.y;
                const int prow = pixBase + mt*16 + row0;
                *(float2*)(out + (size_t)prow      *COUT + col) = v0;
                *(float2*)(out + (size_t)(prow + 8)*COUT + col) = v1;
            }
    }
}

// ---------------- launch ----------------
extern "C" void kernel_launch(void* const* d_in, const int* in_sizes, int n_in,
                              void* d_out, int out_size)
{
    const float *x = nullptr, *bw = nullptr, *sw = nullptr, *bs = nullptr;
    for (int i = 0; i < n_in; i++) {
        switch (in_sizes[i]) {
            case 8*64*64*64:   x  = (const float*)d_in[i]; break;
            case COUT*PATCH:   bw = (const float*)d_in[i]; break;
            case COUT*PATCH*6: sw = (const float*)d_in[i]; break;
            case COUT:         bs = (const float*)d_in[i]; break;
        }
    }
    float* out = (float*)d_out;

    prep_kernel<<<FEAT_BLOCKS + PACK_BLOCKS + 1, 256>>>(x, bw, sw);
    gemm_kernel<<<NPIX / 32, 256, DYN_SMEM>>>(bs, out);
}

// round 16
// speedup vs baseline: 1.5463x; 1.5463x over previous
#include <cuda_runtime.h>
#include <cuda_fp16.h>
#include <cstdint>

// ---------------- problem constants ----------------
#define B_     8
#define CIN    64
#define COUT   128
#define HP     66
#define WP     66
#define FDIM   448               // 64 ch * 7 features
#define KDIM   4032              // 9 taps * 448
#define NPIX   32768
#define PATCH  576
#define NCHUNK 126               // K chunks of 32
#define HCHUNK 63                // chunks per K-group (63 = 7*9)

#define FEAT_BLOCKS ((B_*HP*WP*16)/256)            // 2178 (4 ch/thread)
#define PACK_BLOCKS ((COUT*KDIM + 255)/256)        // 2016

// ---------------- scratch (device globals) ----------------
__device__ __half   g_Fh[(size_t)B_*HP*WP*FDIM];     // 31.2 MB fp16 features
__device__ uint4    g_Wp[(size_t)COUT*KDIM/8];       // 1 MB weights in mma-frag order
__device__ uint32_t g_offA[NCHUNK];                  // per-chunk A element offsets

// ---------------- PTX helpers ----------------
__device__ __forceinline__ uint32_t smem_u32(const void* p) {
    uint32_t a;
    asm("{ .reg .u64 t; cvta.to.shared.u64 t, %1; cvt.u32.u64 %0, t; }"
        : "=r"(a) : "l"(p));
    return a;
}
__device__ __forceinline__ void cpasync16(uint32_t sa, const void* g) {
    asm volatile("cp.async.cg.shared.global [%0], [%1], 16;"
                 :: "r"(sa), "l"(g) : "memory");
}
__device__ __forceinline__ void cp_commit() {
    asm volatile("cp.async.commit_group;" ::: "memory");
}
__device__ __forceinline__ void cp_wait1() {
    asm volatile("cp.async.wait_group 1;" ::: "memory");
}
__device__ __forceinline__ void bar_grp(int id) {
    asm volatile("bar.sync %0, 128;" :: "r"(id) : "memory");
}
__device__ __forceinline__ void ldsm4(uint32_t* r, uint32_t addr) {
    asm volatile("ldmatrix.sync.aligned.m8n8.x4.shared.b16 {%0,%1,%2,%3}, [%4];"
                 : "=r"(r[0]), "=r"(r[1]), "=r"(r[2]), "=r"(r[3]) : "r"(addr));
}
__device__ __forceinline__ void mma16816(float* d, const uint32_t* a, uint32_t b0, uint32_t b1) {
    asm volatile(
        "mma.sync.aligned.m16n8k16.row.col.f32.f16.f16.f32 "
        "{%0,%1,%2,%3}, {%4,%5,%6,%7}, {%8,%9}, {%0,%1,%2,%3};"
        : "+f"(d[0]), "+f"(d[1]), "+f"(d[2]), "+f"(d[3])
        : "r"(a[0]), "r"(a[1]), "r"(a[2]), "r"(a[3]), "r"(b0), "r"(b1));
}
__device__ __forceinline__ uint32_t h2_bits(float a, float b) {
    half2 h = __floats2half2_rn(a, b);
    return *reinterpret_cast<uint32_t*>(&h);
}

// ---------------- truncated-power uniform cubic B-spline + silu ----------------
// B_j(u) = (1/6)[p_j - 4p_{j+1} + 6p_{j+2} - 4p_{j+3} + p_{j+4}],
// p_i = max(u-i,0)^3, u = (v - grid0)/h = 1.5(v+3). All-zero for u>=9 (v>=3),
// and automatically zero for u<=0. Straight-line FMA code (no select chains).
__device__ __forceinline__ void eval_features(float v, float* f)
{
    float u = fminf((v + 3.0f) * 1.5f, 9.5f);   // clamp bounds cancellation noise
    float p[10];
    #pragma unroll
    for (int i = 0; i < 10; i++) {
        float c = fmaxf(u - (float)i, 0.0f);
        p[i] = c * c * c;
    }
    const float s6 = 1.0f / 6.0f;
    const float zf = (u < 9.0f) ? s6 : 0.0f;    // kill bases for v >= 3
    #pragma unroll
    for (int j = 0; j < 6; j++) {
        float b = p[j] + p[j+4] - 4.0f*(p[j+1] + p[j+3]) + 6.0f*p[j+2];
        f[j+1] = b * zf;
    }
    f[0] = v / (1.0f + __expf(-v));             // silu
}

// ---------------- kernel 1: fused feature + weight pack + offset table ----------
// Weight frag layout (R12): frag16 idx = ((chunk*4 + wn)*4 + nt)*32 + lane
//   wn = o>>5 (32-col group), nt = (o>>3)&3, lane = (o&7)*4 + ((k&7)>>1)
//   pos = ((k>>4)&1)*4 + ((k>>3)&1)*2 + (k&1), chunk = k>>5
__global__ void prep_kernel(const float* __restrict__ x,
                            const float* __restrict__ base_w,
                            const float* __restrict__ spline_w)
{
    if (blockIdx.x < FEAT_BLOCKS) {
        int idx = blockIdx.x * blockDim.x + threadIdx.x;  // (pixel, channel-quad)
        int cq = idx & 15;
        int r  = idx >> 4;
        int wp = r % WP; r /= WP;
        int hp = r % HP;
        int b  = r / HP;

        int h = hp - 1, w = wp - 1;
        float4 xv = make_float4(0.f, 0.f, 0.f, 0.f);
        if (h >= 0 && h < 64 && w >= 0 && w < 64)
            xv = *(const float4*)&x[((((size_t)b*64 + h)*64 + w) << 6) + cq*4];

        float f0[7], f1[7], f2[7], f3[7];
        eval_features(xv.x, f0);
        eval_features(xv.y, f1);
        eval_features(xv.z, f2);
        eval_features(xv.w, f3);

        size_t base = (((size_t)b*HP + hp)*WP + wp)*FDIM + cq*4;
        #pragma unroll
        for (int m = 0; m < 7; m++) {
            uint2 pk;
            pk.x = h2_bits(f0[m], f1[m]);
            pk.y = h2_bits(f2[m], f3[m]);
            *(uint2*)&g_Fh[base + (size_t)m*64] = pk;
        }
    } else if (blockIdx.x < FEAT_BLOCKS + PACK_BLOCKS) {
        int idx = (blockIdx.x - FEAT_BLOCKS) * blockDim.x + threadIdx.x; // o*4032+k
        if (idx >= COUT * KDIM) return;
        int o = idx / KDIM;
        int k = idx - o * KDIM;
        int t = k / FDIM;
        int rr = k - t * FDIM;
        int f  = rr >> 6;
        int cc = rr & 63;
        int i  = cc * 9 + t;
        float wv = (f == 0) ? base_w[(size_t)o * PATCH + i]
                            : spline_w[((size_t)o * PATCH + i) * 6 + (f - 1)];

        int chunk = k >> 5;
        int wn    = o >> 5;
        int nt    = (o >> 3) & 3;
        int lane  = ((o & 7) << 2) | ((k & 7) >> 1);
        int pos   = ((k >> 4) & 1) * 4 + ((k >> 3) & 1) * 2 + (k & 1);
        size_t idx16 = (((size_t)chunk*4 + wn)*4 + nt)*32 + lane;
        ((__half*)g_Wp)[idx16 * 8 + pos] = __float2half(wv);
    } else {
        int c = threadIdx.x;
        if (c < NCHUNK) {
            int t  = c / 14;
            int rr = c - t * 14;
            int f  = rr >> 1;
            int c0 = (rr & 1) << 5;
            int ky = t / 3;
            int kx = t - ky * 3;
            g_offA[c] = (uint32_t)((ky * WP + kx) * FDIM + f * 64 + c0);
        }
    }
}

// ---------------- kernel 2: GEMM — EXACT R12 config (best measured: 95.9us) ----
// 1024 CTAs x 256 threads, 2 CTAs/SM. CTA tile: M=32, N=128, K=4032.
// 8 warps = 2 K-groups x 4 N-warps; warp tile M32 x N32. B fragments triple-
// buffered in regs (3x unrolled windows); 9-slot smem A pipeline; cp.wait +
// named group barrier once per 3-chunk window (63 = 7*9).
#define NSLOT  9
#define PITCH  80
#define STAGEB (32*PITCH)                 // 2560 B
#define REGION (NSLOT*STAGEB)             // 23040 B per K-group
#define RED_PITCH 132
#define DYN_SMEM (2*REGION)               // 46080 B (> 32*132*4 = 16896 epilogue)

__global__ void __launch_bounds__(256, 2)
gemm_kernel(const float* __restrict__ bias, float* __restrict__ out)
{
    extern __shared__ char dyn[];
    const uint32_t smbase = smem_u32(dyn);

    const int tid  = threadIdx.x;
    const int wid  = tid >> 5;
    const int lane = tid & 31;
    const int ks   = wid >> 2;              // K-group 0/1
    const int wn   = wid & 3;               // 32-col N group

    const int pixBase = blockIdx.x * 32;
    const int bimg    = pixBase >> 12;
    const int h0      = (pixBase >> 6) & 63;
    const int w0      = pixBase & 63;

    // ---- A cp.async geometry: each K-group's 128 threads load their own chunk
    const int rrow = (tid & 127) >> 2;      // 0..31
    const int seg  = tid & 3;
    const uint32_t baseA = (uint32_t)((((bimg*HP + h0)*WP) + (w0 + rrow))*FDIM) + seg*8;
    const uint32_t dstA  = smbase + ks * REGION + rrow * PITCH + seg * 16;

    // ---- A ldmatrix geometry (4 warps of a K-group share the same fragments)
    const uint32_t pA = smbase + ks * REGION + (lane & 15) * PITCH + (lane >> 4) * 16;

    // ---- B LDG geometry: frag16 idx = ((chunk*4 + wn)*4 + nt)*32 + lane
    const uint4* wpBase = g_Wp + (size_t)wn * 128 + lane;   // chunk stride 512, nt +32
    const int cBase = ks * HCHUNK;

    float acc[2][4][4];
    #pragma unroll
    for (int mt = 0; mt < 2; mt++)
        #pragma unroll
        for (int nt = 0; nt < 4; nt++)
            #pragma unroll
            for (int q = 0; q < 4; q++) acc[mt][nt][q] = 0.0f;

    auto produce = [&](int i, int s) {
        cpasync16(dstA + s * STAGEB, g_Fh + baseA + g_offA[cBase + i]);
    };

    // prologue: windows -2,-1 (chunks 0..2 and 3..5), B chunks 0,1 in regs
    #pragma unroll
    for (int p = 0; p < 3; p++) produce(p, p);
    cp_commit();
    #pragma unroll
    for (int p = 3; p < 6; p++) produce(p, p);
    cp_commit();

    uint4 B0[4], B1[4], B2[4];
    #pragma unroll
    for (int nt = 0; nt < 4; nt++) {
        B0[nt] = wpBase[(size_t)cBase * 512 + nt * 32];
        B1[nt] = wpBase[(size_t)(cBase + 1) * 512 + nt * 32];
    }

    const int barid = ks + 1;

    // one chunk: prefetch B chunk i+2 into bLoad, compute with bUse from slot s
    auto body = [&](int i, int s, uint4* bUse, uint4* bLoad) {
        if (i + 2 < HCHUNK) {
            const uint4* w = wpBase + (size_t)(cBase + i + 2) * 512;
            #pragma unroll
            for (int nt = 0; nt < 4; nt++) bLoad[nt] = w[nt * 32];
        }
        const uint32_t so = s * STAGEB;
        uint32_t a00[4], a10[4], a01[4], a11[4];
        ldsm4(a00, pA + so);                        // mt=0, kk=0
        ldsm4(a10, pA + so + 16*PITCH);             // mt=1, kk=0
        ldsm4(a01, pA + so + 32);                   // mt=0, kk=1
        ldsm4(a11, pA + so + 16*PITCH + 32);        // mt=1, kk=1
        #pragma unroll
        for (int nt = 0; nt < 4; nt++) {
            mma16816(acc[0][nt], a00, bUse[nt].x, bUse[nt].y);
            mma16816(acc[1][nt], a10, bUse[nt].x, bUse[nt].y);
        }
        #pragma unroll
        for (int nt = 0; nt < 4; nt++) {
            mma16816(acc[0][nt], a01, bUse[nt].z, bUse[nt].w);
            mma16816(acc[1][nt], a11, bUse[nt].z, bUse[nt].w);
        }
    };

    // one 3-chunk window starting at local chunk i, reading slots sB..sB+2,
    // producing chunks i+6..i+8 into slots wB..wB+2
    auto window = [&](int i, int sB, int wB) {
        cp_wait1();            // window's own read group fully landed
        bar_grp(barid);        // group-wide visibility + prev-window reads done
        if (i + 6 < HCHUNK) {
            produce(i + 6, wB);
            produce(i + 7, wB + 1);
            produce(i + 8, wB + 2);
        }
        cp_commit();           // empty groups keep wait accounting exact
        body(i,     sB,     B0, B2);
        body(i + 1, sB + 1, B1, B0);
        body(i + 2, sB + 2, B2, B1);
    };

    #pragma unroll 1
    for (int w = 0; w < HCHUNK; w += 9) {   // 63 = 7 * 9
        window(w,     0, 6);
        window(w + 3, 3, 0);
        window(w + 6, 6, 3);
    }

    // ---- epilogue: reduce the two K-group partials via smem, + bias, store ----
    __syncthreads();
    float* red = (float*)dyn;   // [32][RED_PITCH]
    const int colb0 = wn*32 + (lane & 3)*2;
    const int row0  = lane >> 2;

    if (ks == 1) {
        #pragma unroll
        for (int mt = 0; mt < 2; mt++)
            #pragma unroll
            for (int nt = 0; nt < 4; nt++) {
                const int col = colb0 + nt*8;
                *(float2*)&red[(mt*16 + row0    ) * RED_PITCH + col] =
                    make_float2(acc[mt][nt][0], acc[mt][nt][1]);
                *(float2*)&red[(mt*16 + row0 + 8) * RED_PITCH + col] =
                    make_float2(acc[mt][nt][2], acc[mt][nt][3]);
            }
    }
    __syncthreads();
    if (ks == 0) {
        #pragma unroll
        for (int mt = 0; mt < 2; mt++)
            #pragma unroll
            for (int nt = 0; nt < 4; nt++) {
                const int col = colb0 + nt*8;
                const float2 b2 = *(const float2*)(bias + col);
                float2 p0 = *(float2*)&red[(mt*16 + row0    ) * RED_PITCH + col];
                float2 p1 = *(float2*)&red[(mt*16 + row0 + 8) * RED_PITCH + col];
                float2 v0, v1;
                v0.x = acc[mt][nt][0] + p0.x + b2.x;
                v0.y = acc[mt][nt][1] + p0.y + b2.y;
                v1.x = acc[mt][nt][2] + p1.x + b2.x;
                v1.y = acc[mt][nt][3] + p1.y + b2.y;
                const int prow = pixBase + mt*16 + row0;
                *(float2*)(out + (size_t)prow      *COUT + col) = v0;
                *(float2*)(out + (size_t)(prow + 8)*COUT + col) = v1;
            }
    }
}

// ---------------- launch ----------------
extern "C" void kernel_launch(void* const* d_in, const int* in_sizes, int n_in,
                              void* d_out, int out_size)
{
    const float *x = nullptr, *bw = nullptr, *sw = nullptr, *bs = nullptr;
    for (int i = 0; i < n_in; i++) {
        switch (in_sizes[i]) {
            case 8*64*64*64:   x  = (const float*)d_in[i]; break;
            case COUT*PATCH:   bw = (const float*)d_in[i]; break;
            case COUT*PATCH*6: sw = (const float*)d_in[i]; break;
            case COUT:         bs = (const float*)d_in[i]; break;
        }
    }
    float* out = (float*)d_out;

    prep_kernel<<<FEAT_BLOCKS + PACK_BLOCKS + 1, 256>>>(x, bw, sw);
    gemm_kernel<<<NPIX / 32, 256, DYN_SMEM>>>(bs, out);
}